// round 10
// baseline (speedup 1.0000x reference)
#include <cuda_runtime.h>

typedef unsigned long long u64;

#define B_ 4096
#define T_ 128
#define I_ 16
#define H_ 64
#define NB 4      // batches per CTA
#define NTR 128   // 4 warps; thread = (unit j = w*16+(lane&15), k-half s = lane>>4)

// ---- packed f32x2 helpers (sm_100+; ptxas never emits these from C++) ----
__device__ __forceinline__ u64 pk2(float lo, float hi) {
    u64 r; asm("mov.b64 %0, {%1,%2};" : "=l"(r) : "f"(lo), "f"(hi)); return r;
}
__device__ __forceinline__ void upk2(u64 v, float& lo, float& hi) {
    asm("mov.b64 {%0,%1}, %2;" : "=f"(lo), "=f"(hi) : "l"(v));
}
__device__ __forceinline__ u64 fma2(u64 a, u64 b, u64 c) {
    u64 d; asm("fma.rn.f32x2 %0, %1, %2, %3;" : "=l"(d) : "l"(a), "l"(b), "l"(c)); return d;
}
__device__ __forceinline__ u64 mul2(u64 a, u64 b) {
    u64 d; asm("mul.rn.f32x2 %0, %1, %2;" : "=l"(d) : "l"(a), "l"(b)); return d;
}
__device__ __forceinline__ u64 add2(u64 a, u64 b) {
    u64 d; asm("add.rn.f32x2 %0, %1, %2;" : "=l"(d) : "l"(a), "l"(b)); return d;
}
__device__ __forceinline__ float red2(u64 v) { float lo, hi; upk2(v, lo, hi); return lo + hi; }

// exp-based activations (~1e-6/step; tanh.approx's 2^-11 would compound over T=128)
__device__ __forceinline__ float sigmoidf_(float a) { return __fdividef(1.0f, 1.0f + __expf(-a)); }
__device__ __forceinline__ float tanhf_(float a)    { return __fdividef(2.0f, 1.0f + __expf(-2.0f * a)) - 1.0f; }

__global__ void __launch_bounds__(NTR, 3) gru_fused_kernel(
    const float* __restrict__ x,     // [B, T, I]
    const float* __restrict__ w_ih,  // [3H, I]
    const float* __restrict__ w_hh,  // [3H, H]
    const float* __restrict__ b_ih,  // [3H]
    const float* __restrict__ b_hh,  // [3H]
    const float* __restrict__ fc_w,  // [1, H]
    const float* __restrict__ fc_b,  // [1]
    float* __restrict__ out)         // [B]
{
    __shared__ __align__(16) float sx[NB][T_][I_];     // 32 KB: x for 4 batches
    __shared__ __align__(16) float hbuf[NB][2][H_];    // 2 KB: double-buffered h

    const int tid  = threadIdx.x;
    const int lane = tid & 31;
    const int w    = tid >> 5;
    const int j    = w * 16 + (lane & 15);   // hidden unit 0..63
    const int s    = lane >> 4;              // k-half
    const int bBase = blockIdx.x * NB;

    // ---- register-resident weights: rows (j, j+64, j+128), k-cols [32s,32s+32) ----
    u64 whr[16], whz[16], whn[16];           // 48 u64 = 96 regs
    {
        const u64* pr = reinterpret_cast<const u64*>(w_hh + (j          ) * H_ + s * 32);
        const u64* pz = reinterpret_cast<const u64*>(w_hh + (j +     H_ ) * H_ + s * 32);
        const u64* pn = reinterpret_cast<const u64*>(w_hh + (j + 2 * H_ ) * H_ + s * 32);
        #pragma unroll
        for (int k = 0; k < 16; k++) { whr[k] = pr[k]; whz[k] = pz[k]; whn[k] = pn[k]; }
    }
    u64 wir[4], wiz[4], win[4];              // 12 u64 = 24 regs, x-cols [8s,8s+8)
    {
        const u64* qr = reinterpret_cast<const u64*>(w_ih + (j          ) * I_ + s * 8);
        const u64* qz = reinterpret_cast<const u64*>(w_ih + (j +     H_ ) * I_ + s * 8);
        const u64* qn = reinterpret_cast<const u64*>(w_ih + (j + 2 * H_ ) * I_ + s * 8);
        #pragma unroll
        for (int k = 0; k < 4; k++) { qr += 0; wir[k] = qr[k]; wiz[k] = qz[k]; win[k] = qn[k]; }
    }
    // full-scalar biases, applied once in the finishing lane after the butterfly
    const float br  = b_ih[j]           + b_hh[j];
    const float bz  = b_ih[j + H_]      + b_hh[j + H_];
    const float bnx = b_ih[j + 2 * H_];
    const float bnh = b_hh[j + 2 * H_];

    // ---- preload x for NB batches (coalesced, 32 KB) ----
    {
        const u64* gx = reinterpret_cast<const u64*>(x + (size_t)bBase * (T_ * I_));
        u64* sxu = reinterpret_cast<u64*>(sx);
        #pragma unroll 4
        for (int i = tid; i < NB * T_ * I_ / 2; i += NTR) sxu[i] = gx[i];
    }
    for (int k = tid; k < NB * H_; k += NTR) hbuf[k >> 6][0][k & 63] = 0.0f;
    __syncthreads();

    // running x pointer: one row (I_ floats) per step; batch stride T_*I_ floats
    const float* xcur = &sx[0][0][0] + s * 8;

    // One GRU step with compile-time parity PAR: reads hbuf[i][PAR], writes hbuf[i][PAR^1].
#define GRU_STEP(PAR)                                                                 \
    {                                                                                 \
        float fr[NB], fz[NB], fnx[NB], fnh[NB];                                       \
        _Pragma("unroll")                                                             \
        for (int i = 0; i < NB; i++) {                                                \
            const ulonglong2* hp =                                                    \
                reinterpret_cast<const ulonglong2*>(&hbuf[i][PAR][0]) + s * 8;        \
            const ulonglong2* xp =                                                    \
                reinterpret_cast<const ulonglong2*>(xcur + i * (T_ * I_));            \
            ulonglong2 xv0 = xp[0], xv1 = xp[1];                                      \
            /* accumulators start from products: no init MOVs */                      \
            u64 ar0 = mul2(wir[0], xv0.x), ar1 = mul2(wir[1], xv0.y);                 \
            u64 az0 = mul2(wiz[0], xv0.x), az1 = mul2(wiz[1], xv0.y);                 \
            u64 ax  = mul2(win[0], xv0.x);                                            \
            ar0 = fma2(wir[2], xv1.x, ar0); ar1 = fma2(wir[3], xv1.y, ar1);           \
            az0 = fma2(wiz[2], xv1.x, az0); az1 = fma2(wiz[3], xv1.y, az1);           \
            ax  = fma2(win[1], xv0.y, ax);                                            \
            ax  = fma2(win[2], xv1.x, ax);                                            \
            ax  = fma2(win[3], xv1.y, ax);                                            \
            ulonglong2 u0 = hp[0], u1 = hp[1];                                        \
            u64 ah0 = mul2(whn[0], u0.x), ah1 = mul2(whn[1], u0.y);                   \
            ar0 = fma2(whr[0], u0.x, ar0); az0 = fma2(whz[0], u0.x, az0);             \
            ar1 = fma2(whr[1], u0.y, ar1); az1 = fma2(whz[1], u0.y, az1);             \
            ar0 = fma2(whr[2], u1.x, ar0); az0 = fma2(whz[2], u1.x, az0);             \
            ah0 = fma2(whn[2], u1.x, ah0);                                            \
            ar1 = fma2(whr[3], u1.y, ar1); az1 = fma2(whz[3], u1.y, az1);             \
            ah1 = fma2(whn[3], u1.y, ah1);                                            \
            _Pragma("unroll")                                                         \
            for (int m = 1; m < 4; m++) {                                             \
                ulonglong2 v0 = hp[2 * m + 0];                                        \
                ulonglong2 v1 = hp[2 * m + 1];                                        \
                ar0 = fma2(whr[4 * m + 0], v0.x, ar0);                                \
                az0 = fma2(whz[4 * m + 0], v0.x, az0);                                \
                ah0 = fma2(whn[4 * m + 0], v0.x, ah0);                                \
                ar1 = fma2(whr[4 * m + 1], v0.y, ar1);                                \
                az1 = fma2(whz[4 * m + 1], v0.y, az1);                                \
                ah1 = fma2(whn[4 * m + 1], v0.y, ah1);                                \
                ar0 = fma2(whr[4 * m + 2], v1.x, ar0);                                \
                az0 = fma2(whz[4 * m + 2], v1.x, az0);                                \
                ah0 = fma2(whn[4 * m + 2], v1.x, ah0);                                \
                ar1 = fma2(whr[4 * m + 3], v1.y, ar1);                                \
                az1 = fma2(whz[4 * m + 3], v1.y, az1);                                \
                ah1 = fma2(whn[4 * m + 3], v1.y, ah1);                                \
            }                                                                         \
            fr[i]  = red2(add2(ar0, ar1));                                            \
            fz[i]  = red2(add2(az0, az1));                                            \
            fnh[i] = red2(add2(ah0, ah1));                                            \
            fnx[i] = red2(ax);                                                        \
        }                                                                             \
        _Pragma("unroll")                                                             \
        for (int i = 0; i < NB; i++) {                                                \
            fr[i]  += __shfl_xor_sync(0xFFFFFFFFu, fr[i],  16);                       \
            fz[i]  += __shfl_xor_sync(0xFFFFFFFFu, fz[i],  16);                       \
            fnx[i] += __shfl_xor_sync(0xFFFFFFFFu, fnx[i], 16);                       \
            fnh[i] += __shfl_xor_sync(0xFFFFFFFFu, fnh[i], 16);                       \
        }                                                                             \
        _Pragma("unroll")                                                             \
        for (int u = 0; u < 2; u++) {                                                 \
            const int i = s * 2 + u;                                                  \
            const float hold = hbuf[i][PAR][j];                                       \
            const float r = sigmoidf_(fr[i] + br);                                    \
            const float z = sigmoidf_(fz[i] + bz);                                    \
            const float n = tanhf_(fnx[i] + bnx + r * (fnh[i] + bnh));                \
            hbuf[i][PAR ^ 1][j] = n + z * (hold - n);                                 \
        }                                                                             \
        __syncthreads();                                                              \
        xcur += I_;                                                                   \
    }

    #pragma unroll 1
    for (int t = 0; t < T_; t += 2) {
        GRU_STEP(0)
        GRU_STEP(1)
    }
#undef GRU_STEP

    // ---- head: warp w reduces batch w (final h in hbuf[i][0], T even) ----
    float v = hbuf[w][0][lane] * fc_w[lane] + hbuf[w][0][lane + 32] * fc_w[lane + 32];
    #pragma unroll
    for (int o = 16; o > 0; o >>= 1) v += __shfl_xor_sync(0xFFFFFFFFu, v, o);
    if (lane == 0) out[bBase + w] = v + fc_b[0];
}

extern "C" void kernel_launch(void* const* d_in, const int* in_sizes, int n_in,
                              void* d_out, int out_size) {
    const float* x    = (const float*)d_in[0];
    const float* w_ih = (const float*)d_in[1];
    const float* w_hh = (const float*)d_in[2];
    const float* b_ih = (const float*)d_in[3];
    const float* b_hh = (const float*)d_in[4];
    const float* fc_w = (const float*)d_in[5];
    const float* fc_b = (const float*)d_in[6];
    float* out = (float*)d_out;

    gru_fused_kernel<<<B_ / NB, NTR>>>(x, w_ih, w_hh, b_ih, b_hh, fc_w, fc_b, out);
}

// round 11
// speedup vs baseline: 1.2353x; 1.2353x over previous
#include <cuda_runtime.h>

typedef unsigned long long u64;

#define B_ 4096
#define T_ 128
#define I_ 16
#define H_ 64
#define NB 4      // batches per CTA
#define NTR 256   // 8 warps; thread = (unit j = w*8+(lane&7), k-quarter q = lane>>3)

// ---- packed f32x2 helpers (sm_100+; ptxas never emits these from C++) ----
__device__ __forceinline__ u64 pk2(float lo, float hi) {
    u64 r; asm("mov.b64 %0, {%1,%2};" : "=l"(r) : "f"(lo), "f"(hi)); return r;
}
__device__ __forceinline__ void upk2(u64 v, float& lo, float& hi) {
    asm("mov.b64 {%0,%1}, %2;" : "=f"(lo), "=f"(hi) : "l"(v));
}
__device__ __forceinline__ u64 fma2(u64 a, u64 b, u64 c) {
    u64 d; asm("fma.rn.f32x2 %0, %1, %2, %3;" : "=l"(d) : "l"(a), "l"(b), "l"(c)); return d;
}
__device__ __forceinline__ u64 mul2(u64 a, u64 b) {
    u64 d; asm("mul.rn.f32x2 %0, %1, %2;" : "=l"(d) : "l"(a), "l"(b)); return d;
}
__device__ __forceinline__ u64 add2(u64 a, u64 b) {
    u64 d; asm("add.rn.f32x2 %0, %1, %2;" : "=l"(d) : "l"(a), "l"(b)); return d;
}
__device__ __forceinline__ float red2(u64 v) { float lo, hi; upk2(v, lo, hi); return lo + hi; }

// exp-based activations (~1e-6/step; tanh.approx's 2^-11 would compound over T=128)
__device__ __forceinline__ float sigmoidf_(float a) { return __fdividef(1.0f, 1.0f + __expf(-a)); }
__device__ __forceinline__ float tanhf_(float a)    { return __fdividef(2.0f, 1.0f + __expf(-2.0f * a)) - 1.0f; }

// select v[q] with 3 SELs
__device__ __forceinline__ float selq(float a, float b, float c, float d, int q) {
    float x01 = (q & 1) ? b : a;
    float x23 = (q & 1) ? d : c;
    return (q & 2) ? x23 : x01;
}

__global__ void __launch_bounds__(NTR, 2) gru_fused_kernel(
    const float* __restrict__ x,     // [B, T, I]
    const float* __restrict__ w_ih,  // [3H, I]
    const float* __restrict__ w_hh,  // [3H, H]
    const float* __restrict__ b_ih,  // [3H]
    const float* __restrict__ b_hh,  // [3H]
    const float* __restrict__ fc_w,  // [1, H]
    const float* __restrict__ fc_b,  // [1]
    float* __restrict__ out)         // [B]
{
    __shared__ __align__(16) float sx[NB][T_][I_];   // 32 KB: x for 4 batches
    __shared__ __align__(16) float hb[2][NB][H_];    // 2 KB: double-buffered h

    const int tid  = threadIdx.x;
    const int lane = tid & 31;
    const int w    = tid >> 5;           // warp 0..7
    const int q    = lane >> 3;          // k-quarter 0..3; ALSO the batch this lane finishes
    const int j    = w * 8 + (lane & 7); // hidden unit 0..63
    const int bBase = blockIdx.x * NB;

    // ---- register-resident weights: rows (j, j+64, j+128), k-cols [16q,16q+16) ----
    u64 whr[8], whz[8], whn[8];          // 24 u64 = 48 regs
    {
        const u64* pr = reinterpret_cast<const u64*>(w_hh + (j          ) * H_ + q * 16);
        const u64* pz = reinterpret_cast<const u64*>(w_hh + (j +     H_ ) * H_ + q * 16);
        const u64* pn = reinterpret_cast<const u64*>(w_hh + (j + 2 * H_ ) * H_ + q * 16);
        #pragma unroll
        for (int k = 0; k < 8; k++) { whr[k] = pr[k]; whz[k] = pz[k]; whn[k] = pn[k]; }
    }
    u64 wir[2], wiz[2], win[2];          // 6 u64 = 12 regs, x-cols [4q,4q+4)
    {
        const u64* qr = reinterpret_cast<const u64*>(w_ih + (j          ) * I_ + q * 4);
        const u64* qz = reinterpret_cast<const u64*>(w_ih + (j +     H_ ) * I_ + q * 4);
        const u64* qn = reinterpret_cast<const u64*>(w_ih + (j + 2 * H_ ) * I_ + q * 4);
        wir[0] = qr[0]; wir[1] = qr[1];
        wiz[0] = qz[0]; wiz[1] = qz[1];
        win[0] = qn[0]; win[1] = qn[1];
    }
    // scalar biases for this lane's finishing unit j
    const float br  = b_ih[j]           + b_hh[j];
    const float bz  = b_ih[j + H_]      + b_hh[j + H_];
    const float bnx = b_ih[j + 2 * H_];
    const float bnh = b_hh[j + 2 * H_];

    // ---- preload x for NB batches (coalesced, 32 KB) ----
    {
        const u64* gx = reinterpret_cast<const u64*>(x + (size_t)bBase * (T_ * I_));
        u64* sxu = reinterpret_cast<u64*>(sx);
        #pragma unroll 4
        for (int i = tid; i < NB * T_ * I_ / 2; i += NTR) sxu[i] = gx[i];
    }
    if (tid < NB * H_) (&hb[0][0][0])[tid] = 0.0f;   // zero the first read buffer
    __syncthreads();

    const float* hs = &hb[0][0][0];      // read buffer
    float*       hd = &hb[1][0][0];      // write buffer
    const float* xcur = &sx[0][0][0] + q * 4;

    #pragma unroll 1
    for (int t = 0; t < T_; t++) {
        float fr[NB], fz[NB], fnx[NB], fnh[NB];
        #pragma unroll
        for (int i = 0; i < NB; i++) {
            // x-part: 4 floats (this quarter's I-slice)
            const ulonglong2* xp = reinterpret_cast<const ulonglong2*>(xcur + i * (T_ * I_));
            ulonglong2 xv = xp[0];
            u64 ar = mul2(wir[0], xv.x);
            u64 az = mul2(wiz[0], xv.x);
            u64 ax = mul2(win[0], xv.x);
            ar = fma2(wir[1], xv.y, ar);
            az = fma2(wiz[1], xv.y, az);
            ax = fma2(win[1], xv.y, ax);
            // h-part: 16 floats (this quarter's k-slice), 4 LDS.128
            const ulonglong2* hp = reinterpret_cast<const ulonglong2*>(hs + i * H_ + q * 16);
            ulonglong2 v0 = hp[0], v1 = hp[1], v2 = hp[2], v3 = hp[3];
            u64 ah = mul2(whn[0], v0.x);
            ar = fma2(whr[0], v0.x, ar); az = fma2(whz[0], v0.x, az);
            ar = fma2(whr[1], v0.y, ar); az = fma2(whz[1], v0.y, az); ah = fma2(whn[1], v0.y, ah);
            ar = fma2(whr[2], v1.x, ar); az = fma2(whz[2], v1.x, az); ah = fma2(whn[2], v1.x, ah);
            ar = fma2(whr[3], v1.y, ar); az = fma2(whz[3], v1.y, az); ah = fma2(whn[3], v1.y, ah);
            ar = fma2(whr[4], v2.x, ar); az = fma2(whz[4], v2.x, az); ah = fma2(whn[4], v2.x, ah);
            ar = fma2(whr[5], v2.y, ar); az = fma2(whz[5], v2.y, az); ah = fma2(whn[5], v2.y, ah);
            ar = fma2(whr[6], v3.x, ar); az = fma2(whz[6], v3.x, az); ah = fma2(whn[6], v3.x, ah);
            ar = fma2(whr[7], v3.y, ar); az = fma2(whz[7], v3.y, az); ah = fma2(whn[7], v3.y, ah);
            fr[i]  = red2(ar);
            fz[i]  = red2(az);
            fnx[i] = red2(ax);
            fnh[i] = red2(ah);
        }

        // ---- butterfly across k-quarters (in-warp): xor8 then xor16 ----
        #pragma unroll
        for (int i = 0; i < NB; i++) {
            fr[i]  += __shfl_xor_sync(0xFFFFFFFFu, fr[i],  8);
            fz[i]  += __shfl_xor_sync(0xFFFFFFFFu, fz[i],  8);
            fnx[i] += __shfl_xor_sync(0xFFFFFFFFu, fnx[i], 8);
            fnh[i] += __shfl_xor_sync(0xFFFFFFFFu, fnh[i], 8);
        }
        #pragma unroll
        for (int i = 0; i < NB; i++) {
            fr[i]  += __shfl_xor_sync(0xFFFFFFFFu, fr[i],  16);
            fz[i]  += __shfl_xor_sync(0xFFFFFFFFu, fz[i],  16);
            fnx[i] += __shfl_xor_sync(0xFFFFFFFFu, fnx[i], 16);
            fnh[i] += __shfl_xor_sync(0xFFFFFFFFu, fnh[i], 16);
        }

        // ---- lane (q, j) finishes batch q, unit j ----
        const float sr  = selq(fr[0],  fr[1],  fr[2],  fr[3],  q);
        const float sz  = selq(fz[0],  fz[1],  fz[2],  fz[3],  q);
        const float snx = selq(fnx[0], fnx[1], fnx[2], fnx[3], q);
        const float snh = selq(fnh[0], fnh[1], fnh[2], fnh[3], q);
        const float hold = hs[q * H_ + j];
        const float r = sigmoidf_(sr + br);
        const float z = sigmoidf_(sz + bz);
        const float n = tanhf_(snx + bnx + r * (snh + bnh));
        hd[q * H_ + j] = n + z * (hold - n);
        __syncthreads();                  // one barrier per step

        const float* tp = hs; hs = hd; hd = const_cast<float*>(tp);
        xcur += I_;
    }

    // ---- head: warp w (0..3) reduces batch w; final h is in hs (= hb[0], T even) ----
    if (w < NB) {
        float v = hs[w * H_ + lane] * fc_w[lane] + hs[w * H_ + lane + 32] * fc_w[lane + 32];
        #pragma unroll
        for (int o = 16; o > 0; o >>= 1) v += __shfl_xor_sync(0xFFFFFFFFu, v, o);
        if (lane == 0) out[bBase + w] = v + fc_b[0];
    }
}

extern "C" void kernel_launch(void* const* d_in, const int* in_sizes, int n_in,
                              void* d_out, int out_size) {
    const float* x    = (const float*)d_in[0];
    const float* w_ih = (const float*)d_in[1];
    const float* w_hh = (const float*)d_in[2];
    const float* b_ih = (const float*)d_in[3];
    const float* b_hh = (const float*)d_in[4];
    const float* fc_w = (const float*)d_in[5];
    const float* fc_b = (const float*)d_in[6];
    float* out = (float*)d_out;

    gru_fused_kernel<<<B_ / NB, NTR>>>(x, w_ih, w_hh, b_ih, b_hh, fc_w, fc_b, out);
}

// round 14
// speedup vs baseline: 1.2692x; 1.0274x over previous
#include <cuda_runtime.h>

typedef unsigned long long u64;

#define B_ 4096
#define T_ 128
#define I_ 16
#define H_ 64
#define NB 4      // batches per CTA
#define NTR 256   // 8 warps; thread = (unit-pair p = w*4+(lane&3), k-octant o = lane>>2)

// ---- packed f32x2 helpers (sm_100+; ptxas never emits these from C++) ----
__device__ __forceinline__ void upk2(u64 v, float& lo, float& hi) {
    asm("mov.b64 {%0,%1}, %2;" : "=f"(lo), "=f"(hi) : "l"(v));
}
__device__ __forceinline__ u64 fma2(u64 a, u64 b, u64 c) {
    u64 d; asm("fma.rn.f32x2 %0, %1, %2, %3;" : "=l"(d) : "l"(a), "l"(b), "l"(c)); return d;
}
__device__ __forceinline__ u64 mul2(u64 a, u64 b) {
    u64 d; asm("mul.rn.f32x2 %0, %1, %2;" : "=l"(d) : "l"(a), "l"(b)); return d;
}
__device__ __forceinline__ float red2(u64 v) { float lo, hi; upk2(v, lo, hi); return lo + hi; }

// exp-based activations (~1e-6/step; tanh.approx's 2^-11 would compound over T=128)
__device__ __forceinline__ float sigmoidf_(float a) { return __fdividef(1.0f, 1.0f + __expf(-a)); }
__device__ __forceinline__ float tanhf_(float a)    { return __fdividef(2.0f, 1.0f + __expf(-2.0f * a)) - 1.0f; }

__global__ void __launch_bounds__(NTR, 2) gru_fused_kernel(
    const float* __restrict__ x,     // [B, T, I]
    const float* __restrict__ w_ih,  // [3H, I]
    const float* __restrict__ w_hh,  // [3H, H]
    const float* __restrict__ b_ih,  // [3H]
    const float* __restrict__ b_hh,  // [3H]
    const float* __restrict__ fc_w,  // [1, H]
    const float* __restrict__ fc_b,  // [1]
    float* __restrict__ out)         // [B]
{
    __shared__ __align__(16) float sx[NB][T_][I_];   // 32 KB: x for 4 batches
    __shared__ __align__(16) float hb[2][NB][H_];    // 2 KB: double-buffered h

    const int tid  = threadIdx.x;
    const int lane = tid & 31;
    const int w    = tid >> 5;            // warp 0..7
    const int p    = w * 4 + (lane & 3);  // unit pair 0..31 -> units (p, p+32)
    const int o    = lane >> 2;           // k-octant 0..7: k in [8o, 8o+8)
    const int j0   = p, j1 = p + 32;
    const int mu   = o >> 2;              // unit this lane finishes (0->j0, 1->j1)
    const int bb1  = (o >> 1) & 1;        // batch bit1 this lane keeps
    const int bb0  = o & 1;               // batch bit0 this lane keeps
    const int bf   = o & 3;               // batch this lane finishes
    const int jf   = mu ? j1 : j0;
    const int bBase = blockIdx.x * NB;

    // ---- register-resident weights: 6 rows x k-octant = 48 floats ----
    u64 whr0[4], whz0[4], whn0[4], whr1[4], whz1[4], whn1[4];
    {
        const u64* a0 = reinterpret_cast<const u64*>(w_hh + (j0          ) * H_ + o * 8);
        const u64* a1 = reinterpret_cast<const u64*>(w_hh + (j0 +     H_ ) * H_ + o * 8);
        const u64* a2 = reinterpret_cast<const u64*>(w_hh + (j0 + 2 * H_ ) * H_ + o * 8);
        const u64* a3 = reinterpret_cast<const u64*>(w_hh + (j1          ) * H_ + o * 8);
        const u64* a4 = reinterpret_cast<const u64*>(w_hh + (j1 +     H_ ) * H_ + o * 8);
        const u64* a5 = reinterpret_cast<const u64*>(w_hh + (j1 + 2 * H_ ) * H_ + o * 8);
        #pragma unroll
        for (int k = 0; k < 4; k++) {
            whr0[k] = a0[k]; whz0[k] = a1[k]; whn0[k] = a2[k];
            whr1[k] = a3[k]; whz1[k] = a4[k]; whn1[k] = a5[k];
        }
    }
    // x weights: 6 rows x 2 x-cols [2o, 2o+2)
    const u64 wir0 = *reinterpret_cast<const u64*>(w_ih + (j0          ) * I_ + o * 2);
    const u64 wiz0 = *reinterpret_cast<const u64*>(w_ih + (j0 +     H_ ) * I_ + o * 2);
    const u64 win0 = *reinterpret_cast<const u64*>(w_ih + (j0 + 2 * H_ ) * I_ + o * 2);
    const u64 wir1 = *reinterpret_cast<const u64*>(w_ih + (j1          ) * I_ + o * 2);
    const u64 wiz1 = *reinterpret_cast<const u64*>(w_ih + (j1 +     H_ ) * I_ + o * 2);
    const u64 win1 = *reinterpret_cast<const u64*>(w_ih + (j1 + 2 * H_ ) * I_ + o * 2);

    // biases for this lane's finishing (bf, jf)
    const float br  = b_ih[jf]           + b_hh[jf];
    const float bz  = b_ih[jf + H_]      + b_hh[jf + H_];
    const float bnx = b_ih[jf + 2 * H_];
    const float bnh = b_hh[jf + 2 * H_];

    // ---- preload x for NB batches (coalesced, 32 KB) ----
    {
        const u64* gx = reinterpret_cast<const u64*>(x + (size_t)bBase * (T_ * I_));
        u64* sxu = reinterpret_cast<u64*>(sx);
        #pragma unroll 4
        for (int i = tid; i < NB * T_ * I_ / 2; i += NTR) sxu[i] = gx[i];
    }
    (&hb[0][0][0])[tid] = 0.0f;          // NB*H_ == NTR: zero first read buffer
    __syncthreads();

    const float* hs = &hb[0][0][0];      // read buffer
    float*       hd = &hb[1][0][0];      // write buffer
    const float* xcur = &sx[0][0][0] + o * 2;
    float hold = 0.0f;                   // register-carried h for (bf, jf)

    #pragma unroll 1
    for (int t = 0; t < T_; t++) {
        float vals[NB][4];               // per batch: [r, z, nx, nh] for unit mu

        #pragma unroll
        for (int i = 0; i < NB; i++) {
            // h slice: 8 floats = 2 LDS.128
            const ulonglong2* hp = reinterpret_cast<const ulonglong2*>(hs + i * H_ + o * 8);
            ulonglong2 v0 = hp[0], v1 = hp[1];
            // x slice: 2 floats = 1 LDS.64
            const u64 xv = *reinterpret_cast<const u64*>(xcur + i * (T_ * I_));

            u64 ar0 = mul2(wir0, xv), az0 = mul2(wiz0, xv), ax0 = mul2(win0, xv);
            u64 ar1 = mul2(wir1, xv), az1 = mul2(wiz1, xv), ax1 = mul2(win1, xv);
            u64 ah0 = mul2(whn0[0], v0.x), ah1 = mul2(whn1[0], v0.x);
            ar0 = fma2(whr0[0], v0.x, ar0); az0 = fma2(whz0[0], v0.x, az0);
            ar1 = fma2(whr1[0], v0.x, ar1); az1 = fma2(whz1[0], v0.x, az1);
            ar0 = fma2(whr0[1], v0.y, ar0); az0 = fma2(whz0[1], v0.y, az0); ah0 = fma2(whn0[1], v0.y, ah0);
            ar1 = fma2(whr1[1], v0.y, ar1); az1 = fma2(whz1[1], v0.y, az1); ah1 = fma2(whn1[1], v0.y, ah1);
            ar0 = fma2(whr0[2], v1.x, ar0); az0 = fma2(whz0[2], v1.x, az0); ah0 = fma2(whn0[2], v1.x, ah0);
            ar1 = fma2(whr1[2], v1.x, ar1); az1 = fma2(whz1[2], v1.x, az1); ah1 = fma2(whn1[2], v1.x, ah1);
            ar0 = fma2(whr0[3], v1.y, ar0); az0 = fma2(whz0[3], v1.y, az0); ah0 = fma2(whn0[3], v1.y, ah0);
            ar1 = fma2(whr1[3], v1.y, ar1); az1 = fma2(whz1[3], v1.y, az1); ah1 = fma2(whn1[3], v1.y, ah1);

            float s0[4], s1[4];
            s0[0] = red2(ar0); s0[1] = red2(az0); s0[2] = red2(ax0); s0[3] = red2(ah0);
            s1[0] = red2(ar1); s1[1] = red2(az1); s1[2] = red2(ax1); s1[3] = red2(ah1);

            // unit-scatter (xor16): keep unit mu, send the other
            #pragma unroll
            for (int k = 0; k < 4; k++) {
                const float snd = mu ? s0[k] : s1[k];
                const float rcv = __shfl_xor_sync(0xFFFFFFFFu, snd, 16);
                vals[i][k] = (mu ? s1[k] : s0[k]) + rcv;
            }
        }

        // batch-scatter stage 1 (xor8): keep batches with bit1 == bb1
        float kept[2][4];
        #pragma unroll
        for (int bp = 0; bp < 2; bp++)
            #pragma unroll
            for (int k = 0; k < 4; k++) {
                const float snd = bb1 ? vals[bp][k] : vals[2 + bp][k];
                const float rcv = __shfl_xor_sync(0xFFFFFFFFu, snd, 8);
                kept[bp][k] = (bb1 ? vals[2 + bp][k] : vals[bp][k]) + rcv;
            }
        // batch-scatter stage 2 (xor4): keep batch bit0 == bb0
        float fin[4];
        #pragma unroll
        for (int k = 0; k < 4; k++) {
            const float snd = bb0 ? kept[0][k] : kept[1][k];
            const float rcv = __shfl_xor_sync(0xFFFFFFFFu, snd, 4);
            fin[k] = (bb0 ? kept[1][k] : kept[0][k]) + rcv;
        }

        // ---- finish (bf, jf): activations + state update; hold is register-carried ----
        const float r = sigmoidf_(fin[0] + br);
        const float z = sigmoidf_(fin[1] + bz);
        const float n = tanhf_(fin[2] + bnx + r * (fin[3] + bnh));
        hold = n + z * (hold - n);               // (1-z)*n + z*h
        hd[bf * H_ + jf] = hold;
        __syncthreads();                         // one barrier per step

        const float* tp = hs; hs = hd; hd = const_cast<float*>(tp);
        xcur += I_;
    }

    // ---- head: warp w (0..3) reduces batch w; final h is in hs ----
    if (w < NB) {
        float v = hs[w * H_ + lane] * fc_w[lane] + hs[w * H_ + lane + 32] * fc_w[lane + 32];
        #pragma unroll
        for (int off = 16; off > 0; off >>= 1) v += __shfl_xor_sync(0xFFFFFFFFu, v, off);
        if (lane == 0) out[bBase + w] = v + fc_b[0];
    }
}

extern "C" void kernel_launch(void* const* d_in, const int* in_sizes, int n_in,
                              void* d_out, int out_size) {
    const float* x    = (const float*)d_in[0];
    const float* w_ih = (const float*)d_in[1];
    const float* w_hh = (const float*)d_in[2];
    const float* b_ih = (const float*)d_in[3];
    const float* b_hh = (const float*)d_in[4];
    const float* fc_w = (const float*)d_in[5];
    const float* fc_b = (const float*)d_in[6];
    float* out = (float*)d_out;

    gru_fused_kernel<<<B_ / NB, NTR>>>(x, w_ih, w_hh, b_ih, b_hh, fc_w, fc_b, out);
}

// round 15
// speedup vs baseline: 1.3595x; 1.0711x over previous
#include <cuda_runtime.h>

typedef unsigned long long u64;

#define B_ 4096
#define T_ 128
#define I_ 16
#define H_ 64
#define NB 4      // batches per CTA
#define NTR 256   // 8 warps; thread = (unit-pair p = w*4+(lane&3), k-octant o = lane>>2)

// ---- packed f32x2 helpers (sm_100+; ptxas never emits these from C++) ----
__device__ __forceinline__ void upk2(u64 v, float& lo, float& hi) {
    asm("mov.b64 {%0,%1}, %2;" : "=f"(lo), "=f"(hi) : "l"(v));
}
__device__ __forceinline__ u64 fma2(u64 a, u64 b, u64 c) {
    u64 d; asm("fma.rn.f32x2 %0, %1, %2, %3;" : "=l"(d) : "l"(a), "l"(b), "l"(c)); return d;
}
__device__ __forceinline__ u64 mul2(u64 a, u64 b) {
    u64 d; asm("mul.rn.f32x2 %0, %1, %2;" : "=l"(d) : "l"(a), "l"(b)); return d;
}
__device__ __forceinline__ float red2(u64 v) { float lo, hi; upk2(v, lo, hi); return lo + hi; }

// exp-based activations (~1e-6/step; tanh.approx's 2^-11 would compound over T=128)
__device__ __forceinline__ float sigmoidf_(float a) { return __fdividef(1.0f, 1.0f + __expf(-a)); }
__device__ __forceinline__ float tanhf_(float a)    { return __fdividef(2.0f, 1.0f + __expf(-2.0f * a)) - 1.0f; }

__global__ void __launch_bounds__(NTR, 2) gru_fused_kernel(
    const float* __restrict__ x,     // [B, T, I]
    const float* __restrict__ w_ih,  // [3H, I]
    const float* __restrict__ w_hh,  // [3H, H]
    const float* __restrict__ b_ih,  // [3H]
    const float* __restrict__ b_hh,  // [3H]
    const float* __restrict__ fc_w,  // [1, H]
    const float* __restrict__ fc_b,  // [1]
    float* __restrict__ out)         // [B]
{
    __shared__ __align__(16) float sx[NB][T_][I_];   // 32 KB: x for 4 batches
    __shared__ __align__(16) float hb[2][NB][H_];    // 2 KB: double-buffered h

    const int tid  = threadIdx.x;
    const int lane = tid & 31;
    const int w    = tid >> 5;            // warp 0..7
    const int p    = w * 4 + (lane & 3);  // unit pair 0..31 -> units (p, p+32)
    const int o    = lane >> 2;           // k-octant 0..7: k in [8o, 8o+8)
    const int mu   = o >> 2;              // unit this lane finishes (0->p, 1->p+32)
    const int bf   = o & 3;               // batch this lane finishes
    const int jf   = mu ? (p + 32) : p;   // kept unit
    const int jS   = mu ? p : (p + 32);   // sent unit
    const int bBase = blockIdx.x * NB;

    // ---- register-resident weights, XOR-slotted: K = kept unit jf, S = sent unit jS ----
    u64 whrK[4], whzK[4], whnK[4], whrS[4], whzS[4], whnS[4];
    {
        const u64* a0 = reinterpret_cast<const u64*>(w_hh + (jf          ) * H_ + o * 8);
        const u64* a1 = reinterpret_cast<const u64*>(w_hh + (jf +     H_ ) * H_ + o * 8);
        const u64* a2 = reinterpret_cast<const u64*>(w_hh + (jf + 2 * H_ ) * H_ + o * 8);
        const u64* a3 = reinterpret_cast<const u64*>(w_hh + (jS          ) * H_ + o * 8);
        const u64* a4 = reinterpret_cast<const u64*>(w_hh + (jS +     H_ ) * H_ + o * 8);
        const u64* a5 = reinterpret_cast<const u64*>(w_hh + (jS + 2 * H_ ) * H_ + o * 8);
        #pragma unroll
        for (int k = 0; k < 4; k++) {
            whrK[k] = a0[k]; whzK[k] = a1[k]; whnK[k] = a2[k];
            whrS[k] = a3[k]; whzS[k] = a4[k]; whnS[k] = a5[k];
        }
    }
    const u64 wirK = *reinterpret_cast<const u64*>(w_ih + (jf          ) * I_ + o * 2);
    const u64 wizK = *reinterpret_cast<const u64*>(w_ih + (jf +     H_ ) * I_ + o * 2);
    const u64 winK = *reinterpret_cast<const u64*>(w_ih + (jf + 2 * H_ ) * I_ + o * 2);
    const u64 wirS = *reinterpret_cast<const u64*>(w_ih + (jS          ) * I_ + o * 2);
    const u64 wizS = *reinterpret_cast<const u64*>(w_ih + (jS +     H_ ) * I_ + o * 2);
    const u64 winS = *reinterpret_cast<const u64*>(w_ih + (jS + 2 * H_ ) * I_ + o * 2);

    // biases for this lane's finishing (bf, jf)
    const float br  = b_ih[jf]           + b_hh[jf];
    const float bz  = b_ih[jf + H_]      + b_hh[jf + H_];
    const float bnx = b_ih[jf + 2 * H_];
    const float bnh = b_hh[jf + 2 * H_];

    // per-lane XOR-ordered batch offsets (slot i -> batch bf^i)
    int hoff[NB], xoff[NB];
    #pragma unroll
    for (int i = 0; i < NB; i++) {
        hoff[i] = (bf ^ i) * H_ + o * 8;
        xoff[i] = (bf ^ i) * (T_ * I_) + o * 2;
    }

    // ---- preload x for NB batches (coalesced, 32 KB) ----
    {
        const u64* gx = reinterpret_cast<const u64*>(x + (size_t)bBase * (T_ * I_));
        u64* sxu = reinterpret_cast<u64*>(sx);
        #pragma unroll 4
        for (int i = tid; i < NB * T_ * I_ / 2; i += NTR) sxu[i] = gx[i];
    }
    (&hb[0][0][0])[tid] = 0.0f;          // NB*H_ == NTR: zero first read buffer
    __syncthreads();

    const float* hs = &hb[0][0][0];      // read buffer
    float*       hd = &hb[1][0][0];      // write buffer
    const float* xbase = &sx[0][0][0];
    float hold = 0.0f;                   // register-carried h for (bf, jf)

    #pragma unroll 1
    for (int t = 0; t < T_; t++) {
        float vals[NB][4];               // slot i = batch bf^i: [r, z, nx, nh] for unit jf

        #pragma unroll
        for (int i = 0; i < NB; i++) {
            const ulonglong2* hp = reinterpret_cast<const ulonglong2*>(hs + hoff[i]);
            ulonglong2 v0 = hp[0], v1 = hp[1];
            const u64 xv = *reinterpret_cast<const u64*>(xbase + xoff[i]);

            u64 arK = mul2(wirK, xv), azK = mul2(wizK, xv), axK = mul2(winK, xv);
            u64 arS = mul2(wirS, xv), azS = mul2(wizS, xv), axS = mul2(winS, xv);
            u64 ahK = mul2(whnK[0], v0.x), ahS = mul2(whnS[0], v0.x);
            arK = fma2(whrK[0], v0.x, arK); azK = fma2(whzK[0], v0.x, azK);
            arS = fma2(whrS[0], v0.x, arS); azS = fma2(whzS[0], v0.x, azS);
            arK = fma2(whrK[1], v0.y, arK); azK = fma2(whzK[1], v0.y, azK); ahK = fma2(whnK[1], v0.y, ahK);
            arS = fma2(whrS[1], v0.y, arS); azS = fma2(whzS[1], v0.y, azS); ahS = fma2(whnS[1], v0.y, ahS);
            arK = fma2(whrK[2], v1.x, arK); azK = fma2(whzK[2], v1.x, azK); ahK = fma2(whnK[2], v1.x, ahK);
            arS = fma2(whrS[2], v1.x, arS); azS = fma2(whzS[2], v1.x, azS); ahS = fma2(whnS[2], v1.x, ahS);
            arK = fma2(whrK[3], v1.y, arK); azK = fma2(whzK[3], v1.y, azK); ahK = fma2(whnK[3], v1.y, ahK);
            arS = fma2(whrS[3], v1.y, arS); azS = fma2(whzS[3], v1.y, azS); ahS = fma2(whnS[3], v1.y, ahS);

            // unit exchange (xor16): partner's S-slot is MY unit jf. Fixed regs, no SEL.
            vals[i][0] = red2(arK) + __shfl_xor_sync(0xFFFFFFFFu, red2(arS), 16);
            vals[i][1] = red2(azK) + __shfl_xor_sync(0xFFFFFFFFu, red2(azS), 16);
            vals[i][2] = red2(axK) + __shfl_xor_sync(0xFFFFFFFFu, red2(axS), 16);
            vals[i][3] = red2(ahK) + __shfl_xor_sync(0xFFFFFFFFu, red2(ahS), 16);
        }

        // batch-scatter stage xor8 (bit1): keep slots {0,1}; partner slot i+2 = my batch bf^i
        float mid[2][4];
        #pragma unroll
        for (int i = 0; i < 2; i++)
            #pragma unroll
            for (int k = 0; k < 4; k++)
                mid[i][k] = vals[i][k] + __shfl_xor_sync(0xFFFFFFFFu, vals[i + 2][k], 8);

        // batch-scatter stage xor4 (bit0): keep slot 0; partner slot 1 = my batch bf
        float fin[4];
        #pragma unroll
        for (int k = 0; k < 4; k++)
            fin[k] = mid[0][k] + __shfl_xor_sync(0xFFFFFFFFu, mid[1][k], 4);

        // ---- finish (bf, jf): activations + state update; hold is register-carried ----
        const float r = sigmoidf_(fin[0] + br);
        const float z = sigmoidf_(fin[1] + bz);
        const float n = tanhf_(fin[2] + bnx + r * (fin[3] + bnh));
        hold = n + z * (hold - n);               // (1-z)*n + z*h
        hd[bf * H_ + jf] = hold;
        __syncthreads();                         // one barrier per step

        const float* tp = hs; hs = hd; hd = const_cast<float*>(tp);
        xbase += I_;
    }

    // ---- head: warp w (0..3) reduces batch w; final h is in hs (T even) ----
    if (w < NB) {
        float v = hs[w * H_ + lane] * fc_w[lane] + hs[w * H_ + lane + 32] * fc_w[lane + 32];
        #pragma unroll
        for (int off = 16; off > 0; off >>= 1) v += __shfl_xor_sync(0xFFFFFFFFu, v, off);
        if (lane == 0) out[bBase + w] = v + fc_b[0];
    }
}

extern "C" void kernel_launch(void* const* d_in, const int* in_sizes, int n_in,
                              void* d_out, int out_size) {
    const float* x    = (const float*)d_in[0];
    const float* w_ih = (const float*)d_in[1];
    const float* w_hh = (const float*)d_in[2];
    const float* b_ih = (const float*)d_in[3];
    const float* b_hh = (const float*)d_in[4];
    const float* fc_w = (const float*)d_in[5];
    const float* fc_b = (const float*)d_in[6];
    float* out = (float*)d_out;

    gru_fused_kernel<<<B_ / NB, NTR>>>(x, w_ih, w_hh, b_ih, b_hh, fc_w, fc_b, out);
}